// round 12
// baseline (speedup 1.0000x reference)
#include <cuda_runtime.h>
#include <cstdint>

#define T_TOK   4096
#define DMODEL  2048
#define NEXP    32
#define NTOPK   4
#define INTERN  1024
#define NPAIR   (T_TOK * NTOPK)

// ---------------- device scratch (no runtime allocation allowed) ----------------
__device__ int   g_cnt[NEXP];
__device__ int   g_tok[NEXP * T_TOK];
__device__ int   g_pair[NEXP * T_TOK];
__device__ float g_wt[NPAIR];
__device__ float g_h [(size_t)NPAIR * INTERN];      // routed up output (per pair)
__device__ float g_y [(size_t)NPAIR * DMODEL];      // routed down output (per pair, scaled)
__device__ float g_hs[(size_t)T_TOK * 2 * INTERN];  // shared up output

// ---------------- helpers ----------------
__device__ __forceinline__ unsigned f2tf(float x) {
    unsigned u; asm("cvt.rna.tf32.f32 %0, %1;" : "=r"(u) : "f"(x)); return u;
}
__device__ __forceinline__ void mma8(float* d, const unsigned* a, const unsigned* b) {
    asm volatile(
        "mma.sync.aligned.m16n8k8.row.col.f32.tf32.tf32.f32 "
        "{%0,%1,%2,%3},{%4,%5,%6,%7},{%8,%9},{%0,%1,%2,%3};\n"
        : "+f"(d[0]), "+f"(d[1]), "+f"(d[2]), "+f"(d[3])
        : "r"(a[0]), "r"(a[1]), "r"(a[2]), "r"(a[3]), "r"(b[0]), "r"(b[1]));
}

// ---------------- kernel 0: zero expert counters ----------------
__global__ void zero_kernel() {
    if (threadIdx.x < NEXP) g_cnt[threadIdx.x] = 0;
}

// ---------------- kernel 1: gate, 4 tokens per block ----------------
__global__ void __launch_bounds__(128) gate_kernel(const float* __restrict__ X,
                                                   const float* __restrict__ GW) {
    __shared__ float xs[4 * DMODEL];
    __shared__ float logits[4][NEXP];
    const int t0 = blockIdx.x * 4, tid = threadIdx.x;

    const float4* xr = reinterpret_cast<const float4*>(X + (size_t)t0 * DMODEL);
#pragma unroll
    for (int i = 0; i < 16; i++)
        reinterpret_cast<float4*>(xs)[tid + 128 * i] = xr[tid + 128 * i];
    __syncthreads();

    const int e = tid >> 2, p = tid & 3;
    const float4* gw4 = reinterpret_cast<const float4*>(GW + (size_t)e * DMODEL + p * 512);
    const float4* x0 = reinterpret_cast<const float4*>(xs + 0 * DMODEL + p * 512);
    const float4* x1 = reinterpret_cast<const float4*>(xs + 1 * DMODEL + p * 512);
    const float4* x2 = reinterpret_cast<const float4*>(xs + 2 * DMODEL + p * 512);
    const float4* x3 = reinterpret_cast<const float4*>(xs + 3 * DMODEL + p * 512);
    float a0 = 0.f, a1 = 0.f, a2 = 0.f, a3 = 0.f;
#pragma unroll 4
    for (int d = 0; d < 128; d++) {
        const float4 b = gw4[d];
        float4 a;
        a = x0[d]; a0 += a.x * b.x + a.y * b.y + a.z * b.z + a.w * b.w;
        a = x1[d]; a1 += a.x * b.x + a.y * b.y + a.z * b.z + a.w * b.w;
        a = x2[d]; a2 += a.x * b.x + a.y * b.y + a.z * b.z + a.w * b.w;
        a = x3[d]; a3 += a.x * b.x + a.y * b.y + a.z * b.z + a.w * b.w;
    }
#pragma unroll
    for (int o = 2; o; o >>= 1) {
        a0 += __shfl_down_sync(0xffffffffu, a0, o, 4);
        a1 += __shfl_down_sync(0xffffffffu, a1, o, 4);
        a2 += __shfl_down_sync(0xffffffffu, a2, o, 4);
        a3 += __shfl_down_sync(0xffffffffu, a3, o, 4);
    }
    if (p == 0) { logits[0][e] = a0; logits[1][e] = a1; logits[2][e] = a2; logits[3][e] = a3; }
    __syncthreads();

    if (tid < 32) {
        for (int t = 0; t < 4; t++) {
            float v = logits[t][tid];
            float m = v;
#pragma unroll
            for (int o = 16; o; o >>= 1) m = fmaxf(m, __shfl_xor_sync(0xffffffffu, m, o));
            float ex = __expf(v - m), sum = ex;
#pragma unroll
            for (int o = 16; o; o >>= 1) sum += __shfl_xor_sync(0xffffffffu, sum, o);
            float val = ex / sum;
#pragma unroll
            for (int k = 0; k < NTOPK; k++) {
                float bv = val; int bi = tid;
#pragma unroll
                for (int o = 16; o; o >>= 1) {  // argmax, ties -> lower index
                    float ov = __shfl_xor_sync(0xffffffffu, bv, o);
                    int   oi = __shfl_xor_sync(0xffffffffu, bi, o);
                    if (ov > bv || (ov == bv && oi < bi)) { bv = ov; bi = oi; }
                }
                if (tid == 0) {
                    int pr = (t0 + t) * NTOPK + k;
                    g_wt[pr] = bv;
                    int slot = atomicAdd(&g_cnt[bi], 1);
                    g_tok[bi * T_TOK + slot]  = t0 + t;
                    g_pair[bi * T_TOK + slot] = pr;
                }
                if (tid == bi) val = -1e30f;
            }
        }
    }
}

// ================= unified tf32 mma.sync GEMM =================
// CTA tile M=128, N=128, K-chunk=16, DOUBLE-BUFFERED (one barrier per chunk).
// 8 warps as 2(m) x 4(n), warp tile 64x32. Static SMEM 33.5KB; launch_bounds
// (256,2) -> 2 CTAs/SM. Staging: each thread gathers exactly one mma-fragment
// uint4 per region via 4x LDG.32 (row pointers fixed across chunks), converts
// to tf32, and writes ONE conflict-free STS.128 at lane*16B. Mainloop operand
// fetches are conflict-free LDS.128. SMEM layout per buffer:
//   A: [mt 8][slice 2][lane 32] x uint4 = {a0,a1,a2,a3}   (8KB)
//   B: [nt 16][lane 32]         x uint4 = {s0b0,s0b1,s1b0,s1b1} (8KB)
//
// UP mode: B rows interleave W1/W3; C fragment holds (u1,u3) adjacent -> silu
// fused in epilogue, NTOT = N/2 features. DOWN: GEMM * routing weight; ADDY
// additionally adds the 4 routed per-pair y rows (fused combine).
template <bool ROUTED, bool UP, bool ADDY, int KDIM, int NTOT>
__global__ void __launch_bounds__(256, 2) gemm_tc(const float* __restrict__ Xin,
                                                  const float* __restrict__ Bw1,
                                                  const float* __restrict__ Bw3,
                                                  float* __restrict__ OUTp) {
    __shared__ unsigned Asm[2][2048];   // 16KB
    __shared__ unsigned Bsm[2][2048];   // 16KB
    __shared__ int   rmap[128], omap[128];
    __shared__ float smw[128];

    const int e  = blockIdx.z;
    const int m0 = blockIdx.x * 128;
    const int n0 = blockIdx.y * 128;
    int cnt;
    const float *Ap, *W1, *W3 = nullptr;
    float* OUT;
    if constexpr (ROUTED) {
        cnt = g_cnt[e];
        if (m0 >= cnt) return;
        if constexpr (UP) {
            const size_t eo = (size_t)e * INTERN * DMODEL;
            W1 = Bw1 + eo; W3 = Bw3 + eo; Ap = Xin; OUT = g_h;
        } else {
            W1 = Bw1 + (size_t)e * DMODEL * INTERN; Ap = g_h; OUT = g_y;
        }
    } else {
        cnt = T_TOK;
        if constexpr (UP) { W1 = Bw1; W3 = Bw3; Ap = Xin; OUT = g_hs; }
        else              { W1 = Bw1; Ap = g_hs; OUT = OUTp; }
    }

    const int tid = threadIdx.x;
    if (tid < 128) {
        int ic = m0 + tid; if (ic >= cnt) ic = cnt - 1;   // clamp; outputs suppressed
        if constexpr (ROUTED) {
            if constexpr (UP) { rmap[tid] = g_tok[e * T_TOK + ic]; omap[tid] = g_pair[e * T_TOK + ic]; }
            else {
                int pr = g_pair[e * T_TOK + ic];
                rmap[tid] = pr; omap[tid] = pr; smw[tid] = g_wt[pr];
            }
        } else { rmap[tid] = ic; omap[tid] = ic; if constexpr (!UP) smw[tid] = 1.f; }
    }
    __syncthreads();

    const int lane = tid & 31, wid = tid >> 5;
    const int wm = wid >> 2, wn = wid & 3;   // 2 x 4 warp grid, warp tile 64x32
    const int q = lane >> 2, ks = lane & 3;

    // --- staging row pointers (fixed across all K-chunks) ---
    // A: this thread owns fragment lane `lane` of mtile `wid` (both slices):
    //    rows wid*16 + q and +8, cols {ks, ks+4, ks+8, ks+12} within chunk.
    const int ar0 = wid * 16 + q;
    const float* pA0 = Ap + (size_t)rmap[ar0]     * KDIM;
    const float* pA1 = Ap + (size_t)rmap[ar0 + 8] * KDIM;
    // B: this thread owns fragment lane of ntiles wid and wid+8:
    //    rows wid*8 + q and +64, same 4 cols.
    const int bn0 = wid * 8 + q, bn1 = bn0 + 64;
    const float *pB0, *pB1;
    if constexpr (UP) {
        pB0 = ((bn0 & 1) ? W3 : W1) + (size_t)((n0 + bn0) >> 1) * KDIM;
        pB1 = ((bn1 & 1) ? W3 : W1) + (size_t)((n0 + bn1) >> 1) * KDIM;
    } else {
        pB0 = W1 + (size_t)(n0 + bn0) * KDIM;
        pB1 = W1 + (size_t)(n0 + bn1) * KDIM;
    }

    float acc[4][4][4];
#pragma unroll
    for (int mt = 0; mt < 4; mt++)
#pragma unroll
        for (int nt = 0; nt < 4; nt++)
#pragma unroll
            for (int r = 0; r < 4; r++) acc[mt][nt][r] = 0.f;

    float ra0[4], ra1[4], rb0[4], rb1[4];   // prefetch (16 regs)
    auto GLOAD = [&](int kt) {
        const int k0 = kt * 16 + ks;
#pragma unroll
        for (int j = 0; j < 4; j++) {
            ra0[j] = pA0[k0 + 4 * j];
            ra1[j] = pA1[k0 + 4 * j];
            rb0[j] = pB0[k0 + 4 * j];
            rb1[j] = pB1[k0 + 4 * j];
        }
    };
    auto SSTORE = [&](int kt) {
        unsigned* Ab = Asm[kt & 1];
        unsigned* Bb = Bsm[kt & 1];
        // A slice 0: {a0,a1,a2,a3} = {A[r0][ks], A[r1][ks], A[r0][ks+4], A[r1][ks+4]}
        *reinterpret_cast<uint4*>(&Ab[((wid * 2 + 0) * 32 + lane) * 4]) =
            uint4{ f2tf(ra0[0]), f2tf(ra1[0]), f2tf(ra0[1]), f2tf(ra1[1]) };
        // A slice 1: cols +8, +12
        *reinterpret_cast<uint4*>(&Ab[((wid * 2 + 1) * 32 + lane) * 4]) =
            uint4{ f2tf(ra0[2]), f2tf(ra1[2]), f2tf(ra0[3]), f2tf(ra1[3]) };
        // B ntile wid / wid+8: {s0b0, s0b1, s1b0, s1b1}
        *reinterpret_cast<uint4*>(&Bb[((wid    ) * 32 + lane) * 4]) =
            uint4{ f2tf(rb0[0]), f2tf(rb0[1]), f2tf(rb0[2]), f2tf(rb0[3]) };
        *reinterpret_cast<uint4*>(&Bb[((wid + 8) * 32 + lane) * 4]) =
            uint4{ f2tf(rb1[0]), f2tf(rb1[1]), f2tf(rb1[2]), f2tf(rb1[3]) };
    };

    // pipeline prologue: fill buffer 0, prefetch chunk 1
    GLOAD(0);
    SSTORE(0);
    GLOAD(1);
    __syncthreads();

    const int KIT = KDIM / 16;
    for (int kt = 0; kt < KIT; kt++) {
        const unsigned* Ab = Asm[kt & 1];
        const unsigned* Bb = Bsm[kt & 1];

        uint4 bf[4];
#pragma unroll
        for (int nt = 0; nt < 4; nt++)
            bf[nt] = *reinterpret_cast<const uint4*>(&Bb[((wn * 4 + nt) * 32 + lane) * 4]);
#pragma unroll
        for (int sh = 0; sh < 2; sh++) {
            uint4 af[4];
#pragma unroll
            for (int mt = 0; mt < 4; mt++)
                af[mt] = *reinterpret_cast<const uint4*>(
                    &Ab[(((wm * 4 + mt) * 2 + sh) * 32 + lane) * 4]);
#pragma unroll
            for (int mt = 0; mt < 4; mt++)
#pragma unroll
                for (int nt = 0; nt < 4; nt++) {
                    unsigned b2[2];
                    b2[0] = sh ? bf[nt].z : bf[nt].x;
                    b2[1] = sh ? bf[nt].w : bf[nt].y;
                    mma8(acc[mt][nt], reinterpret_cast<const unsigned*>(&af[mt]), b2);
                }
        }

        if (kt + 1 < KIT) SSTORE(kt + 1);   // other buffer; overlaps with mma issue
        if (kt + 2 < KIT) GLOAD(kt + 2);    // latency covered by next chunk's mma
        __syncthreads();                    // single barrier per chunk
    }

    // ---- epilogue ----
#pragma unroll
    for (int mt = 0; mt < 4; mt++) {
        const int lr0 = wm * 64 + mt * 16 + (lane >> 2);
#pragma unroll
        for (int h = 0; h < 2; h++) {
            const int lr = lr0 + 8 * h;
            if (ROUTED && (m0 + lr) >= cnt) continue;
            const size_t orow = (size_t)omap[lr] * NTOT;
            if constexpr (UP) {
#pragma unroll
                for (int nt = 0; nt < 4; nt++) {
                    const int f = ((n0 + (wn * 4 + nt) * 8) >> 1) + (lane & 3);
                    const float u1 = acc[mt][nt][h * 2], u3 = acc[mt][nt][h * 2 + 1];
                    OUT[orow + f] = u1 / (1.f + __expf(-u1)) * u3;
                }
            } else {
                const float w = smw[lr];
#pragma unroll
                for (int nt = 0; nt < 4; nt++) {
                    const int g = n0 + (wn * 4 + nt) * 8 + 2 * (lane & 3);
                    float2 v;
                    v.x = acc[mt][nt][h * 2] * w;
                    v.y = acc[mt][nt][h * 2 + 1] * w;
                    if constexpr (ADDY) {   // fused combine: += 4 routed contributions
                        const size_t t4 = (size_t)omap[lr] * NTOPK;
#pragma unroll
                        for (int k = 0; k < NTOPK; k++) {
                            const float2 yv = *reinterpret_cast<const float2*>(
                                g_y + (t4 + k) * DMODEL + g);
                            v.x += yv.x; v.y += yv.y;
                        }
                    }
                    *reinterpret_cast<float2*>(OUT + orow + g) = v;
                }
            }
        }
    }
}

// ---------------- launch ----------------
extern "C" void kernel_launch(void* const* d_in, const int* in_sizes, int n_in,
                              void* d_out, int out_size) {
    const float* x   = (const float*)d_in[0];
    const float* gw  = (const float*)d_in[1];
    const float* w1  = (const float*)d_in[2];
    const float* w2  = (const float*)d_in[3];
    const float* w3  = (const float*)d_in[4];
    const float* sw1 = (const float*)d_in[5];
    const float* sw2 = (const float*)d_in[6];
    const float* sw3 = (const float*)d_in[7];
    float* out = (float*)d_out;

    zero_kernel<<<1, 32>>>();
    gate_kernel<<<T_TOK / 4, 128>>>(x, gw);

    // routed: up (interleaved W1/W3 -> silu fused), then down (scaled into per-pair y)
    gemm_tc<true,  true,  false, DMODEL, INTERN><<<dim3(T_TOK / 128, (2 * INTERN) / 128, NEXP), 256>>>(x, w1, w3, nullptr);
    gemm_tc<true,  false, false, INTERN, DMODEL><<<dim3(T_TOK / 128, DMODEL / 128, NEXP), 256>>>(x, w2, nullptr, nullptr);

    // shared expert: up, then down writes z + sum_k y directly into d_out (fused combine)
    gemm_tc<false, true,  false, DMODEL, 2 * INTERN><<<dim3(T_TOK / 128, (4 * INTERN) / 128, 1), 256>>>(x, sw1, sw3, nullptr);
    gemm_tc<false, false, true,  2 * INTERN, DMODEL><<<dim3(T_TOK / 128, DMODEL / 128, 1), 256>>>(x, sw2, nullptr, out);
}

// round 13
// speedup vs baseline: 1.0528x; 1.0528x over previous
#include <cuda_runtime.h>
#include <cstdint>

#define T_TOK   4096
#define DMODEL  2048
#define NEXP    32
#define NTOPK   4
#define INTERN  1024
#define NPAIR   (T_TOK * NTOPK)
#define DYN_SMEM 65536   // 2 x (16KB A + 16KB B) double-buffered operands

// ---------------- device scratch (no runtime allocation allowed) ----------------
__device__ int   g_cnt[NEXP];
__device__ int   g_tok[NEXP * T_TOK];
__device__ int   g_pair[NEXP * T_TOK];
__device__ float g_wt[NPAIR];
__device__ float g_h [(size_t)NPAIR * INTERN];      // routed up output (per pair)
__device__ float g_y [(size_t)NPAIR * DMODEL];      // routed down output (per pair, scaled)
__device__ float g_hs[(size_t)T_TOK * 2 * INTERN];  // shared up output

// ---------------- helpers ----------------
__device__ __forceinline__ unsigned f2tf(float x) {
    unsigned u; asm("cvt.rna.tf32.f32 %0, %1;" : "=r"(u) : "f"(x)); return u;
}
__device__ __forceinline__ void mma8(float* d, const unsigned* a, const unsigned* b) {
    asm volatile(
        "mma.sync.aligned.m16n8k8.row.col.f32.tf32.tf32.f32 "
        "{%0,%1,%2,%3},{%4,%5,%6,%7},{%8,%9},{%0,%1,%2,%3};\n"
        : "+f"(d[0]), "+f"(d[1]), "+f"(d[2]), "+f"(d[3])
        : "r"(a[0]), "r"(a[1]), "r"(a[2]), "r"(a[3]), "r"(b[0]), "r"(b[1]));
}

// ---------------- kernel 0: zero expert counters ----------------
__global__ void zero_kernel() {
    if (threadIdx.x < NEXP) g_cnt[threadIdx.x] = 0;
}

// ---------------- kernel 1: gate, 4 tokens per block ----------------
__global__ void __launch_bounds__(128) gate_kernel(const float* __restrict__ X,
                                                   const float* __restrict__ GW) {
    __shared__ float xs[4 * DMODEL];
    __shared__ float logits[4][NEXP];
    const int t0 = blockIdx.x * 4, tid = threadIdx.x;

    const float4* xr = reinterpret_cast<const float4*>(X + (size_t)t0 * DMODEL);
#pragma unroll
    for (int i = 0; i < 16; i++)
        reinterpret_cast<float4*>(xs)[tid + 128 * i] = xr[tid + 128 * i];
    __syncthreads();

    const int e = tid >> 2, p = tid & 3;
    const float4* gw4 = reinterpret_cast<const float4*>(GW + (size_t)e * DMODEL + p * 512);
    const float4* x0 = reinterpret_cast<const float4*>(xs + 0 * DMODEL + p * 512);
    const float4* x1 = reinterpret_cast<const float4*>(xs + 1 * DMODEL + p * 512);
    const float4* x2 = reinterpret_cast<const float4*>(xs + 2 * DMODEL + p * 512);
    const float4* x3 = reinterpret_cast<const float4*>(xs + 3 * DMODEL + p * 512);
    float a0 = 0.f, a1 = 0.f, a2 = 0.f, a3 = 0.f;
#pragma unroll 4
    for (int d = 0; d < 128; d++) {
        const float4 b = gw4[d];
        float4 a;
        a = x0[d]; a0 += a.x * b.x + a.y * b.y + a.z * b.z + a.w * b.w;
        a = x1[d]; a1 += a.x * b.x + a.y * b.y + a.z * b.z + a.w * b.w;
        a = x2[d]; a2 += a.x * b.x + a.y * b.y + a.z * b.z + a.w * b.w;
        a = x3[d]; a3 += a.x * b.x + a.y * b.y + a.z * b.z + a.w * b.w;
    }
#pragma unroll
    for (int o = 2; o; o >>= 1) {
        a0 += __shfl_down_sync(0xffffffffu, a0, o, 4);
        a1 += __shfl_down_sync(0xffffffffu, a1, o, 4);
        a2 += __shfl_down_sync(0xffffffffu, a2, o, 4);
        a3 += __shfl_down_sync(0xffffffffu, a3, o, 4);
    }
    if (p == 0) { logits[0][e] = a0; logits[1][e] = a1; logits[2][e] = a2; logits[3][e] = a3; }
    __syncthreads();

    if (tid < 32) {
        for (int t = 0; t < 4; t++) {
            float v = logits[t][tid];
            float m = v;
#pragma unroll
            for (int o = 16; o; o >>= 1) m = fmaxf(m, __shfl_xor_sync(0xffffffffu, m, o));
            float ex = __expf(v - m), sum = ex;
#pragma unroll
            for (int o = 16; o; o >>= 1) sum += __shfl_xor_sync(0xffffffffu, sum, o);
            float val = ex / sum;
#pragma unroll
            for (int k = 0; k < NTOPK; k++) {
                float bv = val; int bi = tid;
#pragma unroll
                for (int o = 16; o; o >>= 1) {  // argmax, ties -> lower index
                    float ov = __shfl_xor_sync(0xffffffffu, bv, o);
                    int   oi = __shfl_xor_sync(0xffffffffu, bi, o);
                    if (ov > bv || (ov == bv && oi < bi)) { bv = ov; bi = oi; }
                }
                if (tid == 0) {
                    int pr = (t0 + t) * NTOPK + k;
                    g_wt[pr] = bv;
                    int slot = atomicAdd(&g_cnt[bi], 1);
                    g_tok[bi * T_TOK + slot]  = t0 + t;
                    g_pair[bi * T_TOK + slot] = pr;
                }
                if (tid == bi) val = -1e30f;
            }
        }
    }
}

// ================= unified tf32 mma.sync GEMM =================
// CTA tile M=128, N=128, K-chunk=32, DOUBLE-BUFFERED dynamic SMEM (64KB) with
// ONE barrier per chunk: mma on buf[kt&1] overlaps STS into buf[(kt+1)&1] and
// LDG prefetch of chunk kt+2; warps self-overlap each other's phases.
// 8 warps as 2(m) x 4(n), warp tile 64x32. Staging identical to the proven R10
// scheme: coalesced LDG.128 (4 rows x full line per instr), tf32 convert,
// XOR-swizzled scalar STS into mma fragment layout; mainloop operand fetches
// are conflict-free LDS.128.
//
// UP mode: B rows interleave W1/W3; C fragment holds (u1,u3) adjacent -> silu
// fused in epilogue, NTOT = N/2 features. DOWN: GEMM * routing weight; ADDY
// additionally adds the 4 routed per-pair y rows (fused combine).
template <bool ROUTED, bool UP, bool ADDY, int KDIM, int NTOT>
__global__ void __launch_bounds__(256) gemm_tc(const float* __restrict__ Xin,
                                               const float* __restrict__ Bw1,
                                               const float* __restrict__ Bw3,
                                               float* __restrict__ OUTp) {
    extern __shared__ unsigned dynsm[];   // [buf][A 4096 | B 4096] words
    __shared__ int   rmap[128], omap[128];
    __shared__ float smw[128];

    const int e  = blockIdx.z;
    const int m0 = blockIdx.x * 128;
    const int n0 = blockIdx.y * 128;
    int cnt;
    const float *Ap, *W1, *W3 = nullptr;
    float* OUT;
    if constexpr (ROUTED) {
        cnt = g_cnt[e];
        if (m0 >= cnt) return;
        if constexpr (UP) {
            const size_t eo = (size_t)e * INTERN * DMODEL;
            W1 = Bw1 + eo; W3 = Bw3 + eo; Ap = Xin; OUT = g_h;
        } else {
            W1 = Bw1 + (size_t)e * DMODEL * INTERN; Ap = g_h; OUT = g_y;
        }
    } else {
        cnt = T_TOK;
        if constexpr (UP) { W1 = Bw1; W3 = Bw3; Ap = Xin; OUT = g_hs; }
        else              { W1 = Bw1; Ap = g_hs; OUT = OUTp; }
    }

    const int tid = threadIdx.x;
    if (tid < 128) {
        int ic = m0 + tid; if (ic >= cnt) ic = cnt - 1;   // clamp; outputs suppressed
        if constexpr (ROUTED) {
            if constexpr (UP) { rmap[tid] = g_tok[e * T_TOK + ic]; omap[tid] = g_pair[e * T_TOK + ic]; }
            else {
                int pr = g_pair[e * T_TOK + ic];
                rmap[tid] = pr; omap[tid] = pr; smw[tid] = g_wt[pr];
            }
        } else { rmap[tid] = ic; omap[tid] = ic; if constexpr (!UP) smw[tid] = 1.f; }
    }
    __syncthreads();

    const int lane = tid & 31, wid = tid >> 5;
    const int wm = wid >> 2, wn = wid & 3;   // 2 x 4 warp grid, warp tile 64x32

    // staging geometry: 8 threads per row, each owns a float4 column chunk
    const int rbase = tid >> 3, cof = (tid & 7) * 4;
    const float* bsrc;
    if constexpr (UP) bsrc = (rbase & 1) ? W3 : W1;   // B-row parity fixed per thread
    else              bsrc = W1;

    // fragment-layout scatter constants
    const int s_a   = cof >> 3;                 // k-slice of this thread's 4 floats
    const int half  = (cof >> 2) & 1;           // high half of the 8-k slice?
    const int spair = s_a >> 1;
    const int slot  = (s_a & 1) * 2 + half;

    float acc[4][4][4];
#pragma unroll
    for (int mt = 0; mt < 4; mt++)
#pragma unroll
        for (int nt = 0; nt < 4; nt++)
#pragma unroll
            for (int r = 0; r < 4; r++) acc[mt][nt][r] = 0.f;

    float4 pa[4], pb[4];   // prefetch registers (coalesced LDG.128)
    auto GLOAD = [&](int kt) {
        const int k0 = kt * 32;
#pragma unroll
        for (int i = 0; i < 4; i++) {
            const int r = rbase + 32 * i;                       // A row in tile (0..127)
            pa[i] = *reinterpret_cast<const float4*>(Ap + (size_t)rmap[r] * KDIM + k0 + cof);
        }
#pragma unroll
        for (int i = 0; i < 4; i++) {
            const int n = rbase + 32 * i;                       // B row in tile (0..127)
            size_t row;
            if constexpr (UP) row = (size_t)((n0 + n) >> 1);
            else              row = (size_t)(n0 + n);
            pb[i] = *reinterpret_cast<const float4*>(bsrc + row * KDIM + k0 + cof);
        }
    };
    auto SSTORE = [&](int kt) {
        unsigned* Ab = dynsm + (kt & 1) * 8192;
        unsigned* Bb = Ab + 4096;
#pragma unroll
        for (int i = 0; i < 4; i++) {
            const int r = rbase + 32 * i;
            const int mt = r >> 4, rr = r & 15;
            const int q  = (rr >> 3) + 2 * half;
            const int lp = (rr & 7) * 4;
            const unsigned base = (unsigned)(((mt * 4 + s_a) * 32) * 4 + q);
            const float v[4] = { pa[i].x, pa[i].y, pa[i].z, pa[i].w };
#pragma unroll
            for (int e2 = 0; e2 < 4; e2++)
                Ab[base + (((lp + e2) ^ s_a) << 2)] = f2tf(v[e2]);
        }
#pragma unroll
        for (int i = 0; i < 4; i++) {
            const int n  = rbase + 32 * i;
            const int nt = n >> 3;
            const int lp = (n & 7) * 4;
            const unsigned base = (unsigned)(((nt * 2 + spair) * 32) * 4 + slot);
            const float v[4] = { pb[i].x, pb[i].y, pb[i].z, pb[i].w };
#pragma unroll
            for (int e2 = 0; e2 < 4; e2++)
                Bb[base + (((lp + e2) ^ spair) << 2)] = f2tf(v[e2]);
        }
    };

    // pipeline prologue: fill buffer 0, prefetch chunk 1
    GLOAD(0);
    SSTORE(0);
    GLOAD(1);
    __syncthreads();

    const int KIT = KDIM / 32;
    for (int kt = 0; kt < KIT; kt++) {
        const unsigned* Ab = dynsm + (kt & 1) * 8192;
        const unsigned* Bb = Ab + 4096;

#pragma unroll
        for (int sp = 0; sp < 2; sp++) {
            uint4 bf[4];
#pragma unroll
            for (int nt = 0; nt < 4; nt++) {
                const int gnt = wn * 4 + nt;
                bf[nt] = *reinterpret_cast<const uint4*>(
                    &Bb[((gnt * 2 + sp) * 32 + (lane ^ sp)) * 4]);
            }
#pragma unroll
            for (int sh = 0; sh < 2; sh++) {
                const int s = sp * 2 + sh;
                uint4 af[4];
#pragma unroll
                for (int mt = 0; mt < 4; mt++) {
                    const int gmt = wm * 4 + mt;
                    af[mt] = *reinterpret_cast<const uint4*>(
                        &Ab[((gmt * 4 + s) * 32 + (lane ^ s)) * 4]);
                }
#pragma unroll
                for (int mt = 0; mt < 4; mt++)
#pragma unroll
                    for (int nt = 0; nt < 4; nt++) {
                        unsigned b2[2];
                        b2[0] = sh ? bf[nt].z : bf[nt].x;
                        b2[1] = sh ? bf[nt].w : bf[nt].y;
                        mma8(acc[mt][nt], reinterpret_cast<const unsigned*>(&af[mt]), b2);
                    }
            }
        }

        if (kt + 1 < KIT) SSTORE(kt + 1);   // writes the OTHER buffer; overlaps mma
        if (kt + 2 < KIT) GLOAD(kt + 2);    // prefetch; latency hidden by next mma burst
        __syncthreads();                    // single barrier per chunk
    }

    // ---- epilogue ----
#pragma unroll
    for (int mt = 0; mt < 4; mt++) {
        const int lr0 = wm * 64 + mt * 16 + (lane >> 2);
#pragma unroll
        for (int h = 0; h < 2; h++) {
            const int lr = lr0 + 8 * h;
            if (ROUTED && (m0 + lr) >= cnt) continue;
            const size_t orow = (size_t)omap[lr] * NTOT;
            if constexpr (UP) {
#pragma unroll
                for (int nt = 0; nt < 4; nt++) {
                    const int f = ((n0 + (wn * 4 + nt) * 8) >> 1) + (lane & 3);
                    const float u1 = acc[mt][nt][h * 2], u3 = acc[mt][nt][h * 2 + 1];
                    OUT[orow + f] = u1 / (1.f + __expf(-u1)) * u3;
                }
            } else {
                const float w = smw[lr];
#pragma unroll
                for (int nt = 0; nt < 4; nt++) {
                    const int g = n0 + (wn * 4 + nt) * 8 + 2 * (lane & 3);
                    float2 v;
                    v.x = acc[mt][nt][h * 2] * w;
                    v.y = acc[mt][nt][h * 2 + 1] * w;
                    if constexpr (ADDY) {   // fused combine: += 4 routed contributions
                        const size_t t4 = (size_t)omap[lr] * NTOPK;
#pragma unroll
                        for (int k = 0; k < NTOPK; k++) {
                            const float2 yv = *reinterpret_cast<const float2*>(
                                g_y + (t4 + k) * DMODEL + g);
                            v.x += yv.x; v.y += yv.y;
                        }
                    }
                    *reinterpret_cast<float2*>(OUT + orow + g) = v;
                }
            }
        }
    }
}

// ---------------- launch ----------------
extern "C" void kernel_launch(void* const* d_in, const int* in_sizes, int n_in,
                              void* d_out, int out_size) {
    const float* x   = (const float*)d_in[0];
    const float* gw  = (const float*)d_in[1];
    const float* w1  = (const float*)d_in[2];
    const float* w2  = (const float*)d_in[3];
    const float* w3  = (const float*)d_in[4];
    const float* sw1 = (const float*)d_in[5];
    const float* sw2 = (const float*)d_in[6];
    const float* sw3 = (const float*)d_in[7];
    float* out = (float*)d_out;

    // opt-in to 64KB dynamic SMEM (host-side attribute; not a stream operation)
    cudaFuncSetAttribute(gemm_tc<true,  true,  false, DMODEL,     INTERN>,
                         cudaFuncAttributeMaxDynamicSharedMemorySize, DYN_SMEM);
    cudaFuncSetAttribute(gemm_tc<true,  false, false, INTERN,     DMODEL>,
                         cudaFuncAttributeMaxDynamicSharedMemorySize, DYN_SMEM);
    cudaFuncSetAttribute(gemm_tc<false, true,  false, DMODEL,     2 * INTERN>,
                         cudaFuncAttributeMaxDynamicSharedMemorySize, DYN_SMEM);
    cudaFuncSetAttribute(gemm_tc<false, false, true,  2 * INTERN, DMODEL>,
                         cudaFuncAttributeMaxDynamicSharedMemorySize, DYN_SMEM);

    zero_kernel<<<1, 32>>>();
    gate_kernel<<<T_TOK / 4, 128>>>(x, gw);

    // routed: up (interleaved W1/W3 -> silu fused), then down (scaled into per-pair y)
    gemm_tc<true,  true,  false, DMODEL, INTERN>
        <<<dim3(T_TOK / 128, (2 * INTERN) / 128, NEXP), 256, DYN_SMEM>>>(x, w1, w3, nullptr);
    gemm_tc<true,  false, false, INTERN, DMODEL>
        <<<dim3(T_TOK / 128, DMODEL / 128, NEXP), 256, DYN_SMEM>>>(x, w2, nullptr, nullptr);

    // shared expert: up, then down writes z + sum_k y directly into d_out (fused combine)
    gemm_tc<false, true,  false, DMODEL, 2 * INTERN>
        <<<dim3(T_TOK / 128, (4 * INTERN) / 128, 1), 256, DYN_SMEM>>>(x, sw1, sw3, nullptr);
    gemm_tc<false, false, true,  2 * INTERN, DMODEL>
        <<<dim3(T_TOK / 128, DMODEL / 128, 1), 256, DYN_SMEM>>>(x, sw2, nullptr, out);
}

// round 14
// speedup vs baseline: 1.3805x; 1.3113x over previous
#include <cuda_runtime.h>
#include <cstdint>

#define T_TOK   4096
#define DMODEL  2048
#define NEXP    32
#define NTOPK   4
#define INTERN  1024
#define NPAIR   (T_TOK * NTOPK)
#define DYN_SMEM 65536   // 2 x (16KB A + 16KB B) double-buffered operands

// ---------------- device scratch (no runtime allocation allowed) ----------------
__device__ int   g_cnt[NEXP];
__device__ int   g_tok[NEXP * T_TOK];
__device__ int   g_pair[NEXP * T_TOK];
__device__ float g_wt[NPAIR];
__device__ float g_h [(size_t)NPAIR * INTERN];      // routed up output (per pair)
__device__ float g_y [(size_t)NPAIR * DMODEL];      // routed down output (per pair, scaled)
__device__ float g_hs[(size_t)T_TOK * 2 * INTERN];  // shared up output

// ---------------- helpers ----------------
__device__ __forceinline__ unsigned f2tf(float x) {
    unsigned u; asm("cvt.rna.tf32.f32 %0, %1;" : "=r"(u) : "f"(x)); return u;
}
__device__ __forceinline__ void mma8(float* d, const unsigned* a, const unsigned* b) {
    asm volatile(
        "mma.sync.aligned.m16n8k8.row.col.f32.tf32.tf32.f32 "
        "{%0,%1,%2,%3},{%4,%5,%6,%7},{%8,%9},{%0,%1,%2,%3};\n"
        : "+f"(d[0]), "+f"(d[1]), "+f"(d[2]), "+f"(d[3])
        : "r"(a[0]), "r"(a[1]), "r"(a[2]), "r"(a[3]), "r"(b[0]), "r"(b[1]));
}

// ---------------- kernel 0: zero expert counters ----------------
__global__ void zero_kernel() {
    if (threadIdx.x < NEXP) g_cnt[threadIdx.x] = 0;
}

// ---------------- kernel 1: gate, 4 tokens per block ----------------
__global__ void __launch_bounds__(128) gate_kernel(const float* __restrict__ X,
                                                   const float* __restrict__ GW) {
    __shared__ float xs[4 * DMODEL];
    __shared__ float logits[4][NEXP];
    const int t0 = blockIdx.x * 4, tid = threadIdx.x;

    const float4* xr = reinterpret_cast<const float4*>(X + (size_t)t0 * DMODEL);
#pragma unroll
    for (int i = 0; i < 16; i++)
        reinterpret_cast<float4*>(xs)[tid + 128 * i] = xr[tid + 128 * i];
    __syncthreads();

    const int e = tid >> 2, p = tid & 3;
    const float4* gw4 = reinterpret_cast<const float4*>(GW + (size_t)e * DMODEL + p * 512);
    const float4* x0 = reinterpret_cast<const float4*>(xs + 0 * DMODEL + p * 512);
    const float4* x1 = reinterpret_cast<const float4*>(xs + 1 * DMODEL + p * 512);
    const float4* x2 = reinterpret_cast<const float4*>(xs + 2 * DMODEL + p * 512);
    const float4* x3 = reinterpret_cast<const float4*>(xs + 3 * DMODEL + p * 512);
    float a0 = 0.f, a1 = 0.f, a2 = 0.f, a3 = 0.f;
#pragma unroll 4
    for (int d = 0; d < 128; d++) {
        const float4 b = gw4[d];
        float4 a;
        a = x0[d]; a0 += a.x * b.x + a.y * b.y + a.z * b.z + a.w * b.w;
        a = x1[d]; a1 += a.x * b.x + a.y * b.y + a.z * b.z + a.w * b.w;
        a = x2[d]; a2 += a.x * b.x + a.y * b.y + a.z * b.z + a.w * b.w;
        a = x3[d]; a3 += a.x * b.x + a.y * b.y + a.z * b.z + a.w * b.w;
    }
#pragma unroll
    for (int o = 2; o; o >>= 1) {
        a0 += __shfl_down_sync(0xffffffffu, a0, o, 4);
        a1 += __shfl_down_sync(0xffffffffu, a1, o, 4);
        a2 += __shfl_down_sync(0xffffffffu, a2, o, 4);
        a3 += __shfl_down_sync(0xffffffffu, a3, o, 4);
    }
    if (p == 0) { logits[0][e] = a0; logits[1][e] = a1; logits[2][e] = a2; logits[3][e] = a3; }
    __syncthreads();

    if (tid < 32) {
        for (int t = 0; t < 4; t++) {
            float v = logits[t][tid];
            float m = v;
#pragma unroll
            for (int o = 16; o; o >>= 1) m = fmaxf(m, __shfl_xor_sync(0xffffffffu, m, o));
            float ex = __expf(v - m), sum = ex;
#pragma unroll
            for (int o = 16; o; o >>= 1) sum += __shfl_xor_sync(0xffffffffu, sum, o);
            float val = ex / sum;
#pragma unroll
            for (int k = 0; k < NTOPK; k++) {
                float bv = val; int bi = tid;
#pragma unroll
                for (int o = 16; o; o >>= 1) {  // argmax, ties -> lower index
                    float ov = __shfl_xor_sync(0xffffffffu, bv, o);
                    int   oi = __shfl_xor_sync(0xffffffffu, bi, o);
                    if (ov > bv || (ov == bv && oi < bi)) { bv = ov; bi = oi; }
                }
                if (tid == 0) {
                    int pr = (t0 + t) * NTOPK + k;
                    g_wt[pr] = bv;
                    int slot = atomicAdd(&g_cnt[bi], 1);
                    g_tok[bi * T_TOK + slot]  = t0 + t;
                    g_pair[bi * T_TOK + slot] = pr;
                }
                if (tid == bi) val = -1e30f;
            }
        }
    }
}

// ================= unified tf32 mma.sync GEMM =================
// CTA tile M=128, N=128, K-chunk=32, DOUBLE-BUFFERED dynamic SMEM (64KB) with
// ONE barrier per chunk: mma on buf[kt&1] overlaps STS into buf[(kt+1)&1] and
// LDG prefetch of chunk kt+2; warps self-overlap each other's phases.
// 8 warps as 2(m) x 4(n), warp tile 64x32. Staging identical to the proven R10
// scheme: coalesced LDG.128 (4 rows x full line per instr), tf32 convert,
// XOR-swizzled scalar STS into mma fragment layout; mainloop operand fetches
// are conflict-free LDS.128.
//
// UP mode: B rows interleave W1/W3; C fragment holds (u1,u3) adjacent -> silu
// fused in epilogue, NTOT = N/2 features. DOWN: GEMM * routing weight; ADDY
// additionally adds the 4 routed per-pair y rows (fused combine).
template <bool ROUTED, bool UP, bool ADDY, int KDIM, int NTOT>
__global__ void __launch_bounds__(256) gemm_tc(const float* __restrict__ Xin,
                                               const float* __restrict__ Bw1,
                                               const float* __restrict__ Bw3,
                                               float* __restrict__ OUTp) {
    extern __shared__ unsigned dynsm[];   // [buf][A 4096 | B 4096] words
    __shared__ int   rmap[128], omap[128];
    __shared__ float smw[128];

    const int e  = blockIdx.z;
    const int m0 = blockIdx.x * 128;
    const int n0 = blockIdx.y * 128;
    int cnt;
    const float *Ap, *W1, *W3 = nullptr;
    float* OUT;
    if constexpr (ROUTED) {
        cnt = g_cnt[e];
        if (m0 >= cnt) return;
        if constexpr (UP) {
            const size_t eo = (size_t)e * INTERN * DMODEL;
            W1 = Bw1 + eo; W3 = Bw3 + eo; Ap = Xin; OUT = g_h;
        } else {
            W1 = Bw1 + (size_t)e * DMODEL * INTERN; Ap = g_h; OUT = g_y;
        }
    } else {
        cnt = T_TOK;
        if constexpr (UP) { W1 = Bw1; W3 = Bw3; Ap = Xin; OUT = g_hs; }
        else              { W1 = Bw1; Ap = g_hs; OUT = OUTp; }
    }

    const int tid = threadIdx.x;
    if (tid < 128) {
        int ic = m0 + tid; if (ic >= cnt) ic = cnt - 1;   // clamp; outputs suppressed
        if constexpr (ROUTED) {
            if constexpr (UP) { rmap[tid] = g_tok[e * T_TOK + ic]; omap[tid] = g_pair[e * T_TOK + ic]; }
            else {
                int pr = g_pair[e * T_TOK + ic];
                rmap[tid] = pr; omap[tid] = pr; smw[tid] = g_wt[pr];
            }
        } else { rmap[tid] = ic; omap[tid] = ic; if constexpr (!UP) smw[tid] = 1.f; }
    }
    __syncthreads();

    const int lane = tid & 31, wid = tid >> 5;
    const int wm = wid >> 2, wn = wid & 3;   // 2 x 4 warp grid, warp tile 64x32

    // staging geometry: 8 threads per row, each owns a float4 column chunk
    const int rbase = tid >> 3, cof = (tid & 7) * 4;
    const float* bsrc;
    if constexpr (UP) bsrc = (rbase & 1) ? W3 : W1;   // B-row parity fixed per thread
    else              bsrc = W1;

    // fragment-layout scatter constants
    const int s_a   = cof >> 3;                 // k-slice of this thread's 4 floats
    const int half  = (cof >> 2) & 1;           // high half of the 8-k slice?
    const int spair = s_a >> 1;
    const int slot  = (s_a & 1) * 2 + half;

    float acc[4][4][4];
#pragma unroll
    for (int mt = 0; mt < 4; mt++)
#pragma unroll
        for (int nt = 0; nt < 4; nt++)
#pragma unroll
            for (int r = 0; r < 4; r++) acc[mt][nt][r] = 0.f;

    float4 pa[4], pb[4];   // prefetch registers (coalesced LDG.128)
    auto GLOAD = [&](int kt) {
        const int k0 = kt * 32;
#pragma unroll
        for (int i = 0; i < 4; i++) {
            const int r = rbase + 32 * i;                       // A row in tile (0..127)
            pa[i] = *reinterpret_cast<const float4*>(Ap + (size_t)rmap[r] * KDIM + k0 + cof);
        }
#pragma unroll
        for (int i = 0; i < 4; i++) {
            const int n = rbase + 32 * i;                       // B row in tile (0..127)
            size_t row;
            if constexpr (UP) row = (size_t)((n0 + n) >> 1);
            else              row = (size_t)(n0 + n);
            pb[i] = *reinterpret_cast<const float4*>(bsrc + row * KDIM + k0 + cof);
        }
    };
    auto SSTORE = [&](int kt) {
        unsigned* Ab = dynsm + (kt & 1) * 8192;
        unsigned* Bb = Ab + 4096;
#pragma unroll
        for (int i = 0; i < 4; i++) {
            const int r = rbase + 32 * i;
            const int mt = r >> 4, rr = r & 15;
            const int q  = (rr >> 3) + 2 * half;
            const int lp = (rr & 7) * 4;
            const unsigned base = (unsigned)(((mt * 4 + s_a) * 32) * 4 + q);
            const float v[4] = { pa[i].x, pa[i].y, pa[i].z, pa[i].w };
#pragma unroll
            for (int e2 = 0; e2 < 4; e2++)
                Ab[base + (((lp + e2) ^ s_a) << 2)] = f2tf(v[e2]);
        }
#pragma unroll
        for (int i = 0; i < 4; i++) {
            const int n  = rbase + 32 * i;
            const int nt = n >> 3;
            const int lp = (n & 7) * 4;
            const unsigned base = (unsigned)(((nt * 2 + spair) * 32) * 4 + slot);
            const float v[4] = { pb[i].x, pb[i].y, pb[i].z, pb[i].w };
#pragma unroll
            for (int e2 = 0; e2 < 4; e2++)
                Bb[base + (((lp + e2) ^ spair) << 2)] = f2tf(v[e2]);
        }
    };

    // pipeline prologue: fill buffer 0, prefetch chunk 1
    GLOAD(0);
    SSTORE(0);
    GLOAD(1);
    __syncthreads();

    const int KIT = KDIM / 32;
    for (int kt = 0; kt < KIT; kt++) {
        const unsigned* Ab = dynsm + (kt & 1) * 8192;
        const unsigned* Bb = Ab + 4096;

#pragma unroll
        for (int sp = 0; sp < 2; sp++) {
            uint4 bf[4];
#pragma unroll
            for (int nt = 0; nt < 4; nt++) {
                const int gnt = wn * 4 + nt;
                bf[nt] = *reinterpret_cast<const uint4*>(
                    &Bb[((gnt * 2 + sp) * 32 + (lane ^ sp)) * 4]);
            }
#pragma unroll
            for (int sh = 0; sh < 2; sh++) {
                const int s = sp * 2 + sh;
                uint4 af[4];
#pragma unroll
                for (int mt = 0; mt < 4; mt++) {
                    const int gmt = wm * 4 + mt;
                    af[mt] = *reinterpret_cast<const uint4*>(
                        &Ab[((gmt * 4 + s) * 32 + (lane ^ s)) * 4]);
                }
#pragma unroll
                for (int mt = 0; mt < 4; mt++)
#pragma unroll
                    for (int nt = 0; nt < 4; nt++) {
                        unsigned b2[2];
                        b2[0] = sh ? bf[nt].z : bf[nt].x;
                        b2[1] = sh ? bf[nt].w : bf[nt].y;
                        mma8(acc[mt][nt], reinterpret_cast<const unsigned*>(&af[mt]), b2);
                    }
            }
        }

        if (kt + 1 < KIT) SSTORE(kt + 1);   // writes the OTHER buffer; overlaps mma
        if (kt + 2 < KIT) GLOAD(kt + 2);    // prefetch; latency hidden by next mma burst
        __syncthreads();                    // single barrier per chunk
    }

    // ---- epilogue ----
#pragma unroll
    for (int mt = 0; mt < 4; mt++) {
        const int lr0 = wm * 64 + mt * 16 + (lane >> 2);
#pragma unroll
        for (int h = 0; h < 2; h++) {
            const int lr = lr0 + 8 * h;
            if (ROUTED && (m0 + lr) >= cnt) continue;
            const size_t orow = (size_t)omap[lr] * NTOT;
            if constexpr (UP) {
#pragma unroll
                for (int nt = 0; nt < 4; nt++) {
                    const int f = ((n0 + (wn * 4 + nt) * 8) >> 1) + (lane & 3);
                    const float u1 = acc[mt][nt][h * 2], u3 = acc[mt][nt][h * 2 + 1];
                    OUT[orow + f] = u1 / (1.f + __expf(-u1)) * u3;
                }
            } else {
                const float w = smw[lr];
#pragma unroll
                for (int nt = 0; nt < 4; nt++) {
                    const int g = n0 + (wn * 4 + nt) * 8 + 2 * (lane & 3);
                    float2 v;
                    v.x = acc[mt][nt][h * 2] * w;
                    v.y = acc[mt][nt][h * 2 + 1] * w;
                    if constexpr (ADDY) {   // fused combine: += 4 routed contributions
                        const size_t t4 = (size_t)omap[lr] * NTOPK;
#pragma unroll
                        for (int k = 0; k < NTOPK; k++) {
                            const float2 yv = *reinterpret_cast<const float2*>(
                                g_y + (t4 + k) * DMODEL + g);
                            v.x += yv.x; v.y += yv.y;
                        }
                    }
                    *reinterpret_cast<float2*>(OUT + orow + g) = v;
                }
            }
        }
    }
}

// ---------------- launch ----------------
extern "C" void kernel_launch(void* const* d_in, const int* in_sizes, int n_in,
                              void* d_out, int out_size) {
    const float* x   = (const float*)d_in[0];
    const float* gw  = (const float*)d_in[1];
    const float* w1  = (const float*)d_in[2];
    const float* w2  = (const float*)d_in[3];
    const float* w3  = (const float*)d_in[4];
    const float* sw1 = (const float*)d_in[5];
    const float* sw2 = (const float*)d_in[6];
    const float* sw3 = (const float*)d_in[7];
    float* out = (float*)d_out;

    // opt-in to 64KB dynamic SMEM (host-side attribute; not a stream operation)
    cudaFuncSetAttribute(gemm_tc<true,  true,  false, DMODEL,     INTERN>,
                         cudaFuncAttributeMaxDynamicSharedMemorySize, DYN_SMEM);
    cudaFuncSetAttribute(gemm_tc<true,  false, false, INTERN,     DMODEL>,
                         cudaFuncAttributeMaxDynamicSharedMemorySize, DYN_SMEM);
    cudaFuncSetAttribute(gemm_tc<false, true,  false, DMODEL,     2 * INTERN>,
                         cudaFuncAttributeMaxDynamicSharedMemorySize, DYN_SMEM);
    cudaFuncSetAttribute(gemm_tc<false, false, true,  2 * INTERN, DMODEL>,
                         cudaFuncAttributeMaxDynamicSharedMemorySize, DYN_SMEM);

    zero_kernel<<<1, 32>>>();
    gate_kernel<<<T_TOK / 4, 128>>>(x, gw);

    // routed: up (interleaved W1/W3 -> silu fused), then down (scaled into per-pair y)
    gemm_tc<true,  true,  false, DMODEL, INTERN>
        <<<dim3(T_TOK / 128, (2 * INTERN) / 128, NEXP), 256, DYN_SMEM>>>(x, w1, w3, nullptr);
    gemm_tc<true,  false, false, INTERN, DMODEL>
        <<<dim3(T_TOK / 128, DMODEL / 128, NEXP), 256, DYN_SMEM>>>(x, w2, nullptr, nullptr);

    // shared expert: up, then down writes z + sum_k y directly into d_out (fused combine)
    gemm_tc<false, true,  false, DMODEL, 2 * INTERN>
        <<<dim3(T_TOK / 128, (4 * INTERN) / 128, 1), 256, DYN_SMEM>>>(x, sw1, sw3, nullptr);
    gemm_tc<false, false, true,  2 * INTERN, DMODEL>
        <<<dim3(T_TOK / 128, DMODEL / 128, 1), 256, DYN_SMEM>>>(x, sw2, nullptr, out);
}

// round 15
// speedup vs baseline: 1.4167x; 1.0262x over previous
#include <cuda_runtime.h>
#include <cstdint>

#define T_TOK   4096
#define DMODEL  2048
#define NEXP    32
#define NTOPK   4
#define INTERN  1024
#define NPAIR   (T_TOK * NTOPK)
#define DYN_SMEM 65536   // 2 x (16KB A + 16KB B) double-buffered operands

// ---------------- device scratch (no runtime allocation allowed) ----------------
__device__ int   g_cnt[NEXP];
__device__ int   g_tok[NEXP * T_TOK];
__device__ int   g_pair[NEXP * T_TOK];
__device__ float g_wt[NPAIR];
__device__ float g_h [(size_t)NPAIR * INTERN];      // routed up output (per pair)
__device__ float g_y [(size_t)NPAIR * DMODEL];      // routed down output (per pair, scaled)
__device__ float g_hs[(size_t)T_TOK * 2 * INTERN];  // shared up output

// ---------------- helpers ----------------
__device__ __forceinline__ unsigned f2tf(float x) {
    unsigned u; asm("cvt.rna.tf32.f32 %0, %1;" : "=r"(u) : "f"(x)); return u;
}
__device__ __forceinline__ void mma8(float* d, const unsigned* a, const unsigned* b) {
    asm volatile(
        "mma.sync.aligned.m16n8k8.row.col.f32.tf32.tf32.f32 "
        "{%0,%1,%2,%3},{%4,%5,%6,%7},{%8,%9},{%0,%1,%2,%3};\n"
        : "+f"(d[0]), "+f"(d[1]), "+f"(d[2]), "+f"(d[3])
        : "r"(a[0]), "r"(a[1]), "r"(a[2]), "r"(a[3]), "r"(b[0]), "r"(b[1]));
}

// ---------------- kernel 0: zero expert counters ----------------
__global__ void zero_kernel() {
    if (threadIdx.x < NEXP) g_cnt[threadIdx.x] = 0;
}

// ---------------- kernel 1: gate, 4 tokens per block ----------------
__global__ void __launch_bounds__(128) gate_kernel(const float* __restrict__ X,
                                                   const float* __restrict__ GW) {
    __shared__ float xs[4 * DMODEL];
    __shared__ float logits[4][NEXP];
    const int t0 = blockIdx.x * 4, tid = threadIdx.x;

    const float4* xr = reinterpret_cast<const float4*>(X + (size_t)t0 * DMODEL);
#pragma unroll
    for (int i = 0; i < 16; i++)
        reinterpret_cast<float4*>(xs)[tid + 128 * i] = xr[tid + 128 * i];
    __syncthreads();

    const int e = tid >> 2, p = tid & 3;
    const float4* gw4 = reinterpret_cast<const float4*>(GW + (size_t)e * DMODEL + p * 512);
    const float4* x0 = reinterpret_cast<const float4*>(xs + 0 * DMODEL + p * 512);
    const float4* x1 = reinterpret_cast<const float4*>(xs + 1 * DMODEL + p * 512);
    const float4* x2 = reinterpret_cast<const float4*>(xs + 2 * DMODEL + p * 512);
    const float4* x3 = reinterpret_cast<const float4*>(xs + 3 * DMODEL + p * 512);
    float a0 = 0.f, a1 = 0.f, a2 = 0.f, a3 = 0.f;
#pragma unroll 4
    for (int d = 0; d < 128; d++) {
        const float4 b = gw4[d];
        float4 a;
        a = x0[d]; a0 += a.x * b.x + a.y * b.y + a.z * b.z + a.w * b.w;
        a = x1[d]; a1 += a.x * b.x + a.y * b.y + a.z * b.z + a.w * b.w;
        a = x2[d]; a2 += a.x * b.x + a.y * b.y + a.z * b.z + a.w * b.w;
        a = x3[d]; a3 += a.x * b.x + a.y * b.y + a.z * b.z + a.w * b.w;
    }
#pragma unroll
    for (int o = 2; o; o >>= 1) {
        a0 += __shfl_down_sync(0xffffffffu, a0, o, 4);
        a1 += __shfl_down_sync(0xffffffffu, a1, o, 4);
        a2 += __shfl_down_sync(0xffffffffu, a2, o, 4);
        a3 += __shfl_down_sync(0xffffffffu, a3, o, 4);
    }
    if (p == 0) { logits[0][e] = a0; logits[1][e] = a1; logits[2][e] = a2; logits[3][e] = a3; }
    __syncthreads();

    if (tid < 32) {
        for (int t = 0; t < 4; t++) {
            float v = logits[t][tid];
            float m = v;
#pragma unroll
            for (int o = 16; o; o >>= 1) m = fmaxf(m, __shfl_xor_sync(0xffffffffu, m, o));
            float ex = __expf(v - m), sum = ex;
#pragma unroll
            for (int o = 16; o; o >>= 1) sum += __shfl_xor_sync(0xffffffffu, sum, o);
            float val = ex / sum;
#pragma unroll
            for (int k = 0; k < NTOPK; k++) {
                float bv = val; int bi = tid;
#pragma unroll
                for (int o = 16; o; o >>= 1) {  // argmax, ties -> lower index
                    float ov = __shfl_xor_sync(0xffffffffu, bv, o);
                    int   oi = __shfl_xor_sync(0xffffffffu, bi, o);
                    if (ov > bv || (ov == bv && oi < bi)) { bv = ov; bi = oi; }
                }
                if (tid == 0) {
                    int pr = (t0 + t) * NTOPK + k;
                    g_wt[pr] = bv;
                    int slot = atomicAdd(&g_cnt[bi], 1);
                    g_tok[bi * T_TOK + slot]  = t0 + t;
                    g_pair[bi * T_TOK + slot] = pr;
                }
                if (tid == bi) val = -1e30f;
            }
        }
    }
}

// ================= unified tf32 mma.sync GEMM =================
// CTA tile M=128, N=128, K-chunk=32, DOUBLE-BUFFERED dynamic SMEM (64KB), one
// barrier per chunk. __launch_bounds__(256,2) -> 2 CTAs/SM so each CTA's
// staging/barrier bubbles are filled by the other's mma bursts.
// Register trick: the mma burst is split into its two sp-halves and SSTORE /
// GLOAD are placed BETWEEN them, so the 32 prefetch regs (pa/pb) are dead
// during the second half -> fits the 128-reg budget without spilling acc.
// Staging = proven R10/R14 scheme: coalesced LDG.128, tf32 convert,
// XOR-swizzled STS into mma fragment layout; mainloop fetches are
// conflict-free LDS.128.
//
// UP mode: B rows interleave W1/W3; C fragment holds (u1,u3) adjacent -> silu
// fused in epilogue, NTOT = N/2 features. DOWN: GEMM * routing weight; ADDY
// additionally adds the 4 routed per-pair y rows (fused combine).
template <bool ROUTED, bool UP, bool ADDY, int KDIM, int NTOT>
__global__ void __launch_bounds__(256, 2) gemm_tc(const float* __restrict__ Xin,
                                                  const float* __restrict__ Bw1,
                                                  const float* __restrict__ Bw3,
                                                  float* __restrict__ OUTp) {
    extern __shared__ unsigned dynsm[];   // [buf][A 4096 | B 4096] words
    __shared__ int   rmap[128], omap[128];
    __shared__ float smw[128];

    const int e  = blockIdx.z;
    const int m0 = blockIdx.x * 128;
    const int n0 = blockIdx.y * 128;
    int cnt;
    const float *Ap, *W1, *W3 = nullptr;
    float* OUT;
    if constexpr (ROUTED) {
        cnt = g_cnt[e];
        if (m0 >= cnt) return;
        if constexpr (UP) {
            const size_t eo = (size_t)e * INTERN * DMODEL;
            W1 = Bw1 + eo; W3 = Bw3 + eo; Ap = Xin; OUT = g_h;
        } else {
            W1 = Bw1 + (size_t)e * DMODEL * INTERN; Ap = g_h; OUT = g_y;
        }
    } else {
        cnt = T_TOK;
        if constexpr (UP) { W1 = Bw1; W3 = Bw3; Ap = Xin; OUT = g_hs; }
        else              { W1 = Bw1; Ap = g_hs; OUT = OUTp; }
    }

    const int tid = threadIdx.x;
    if (tid < 128) {
        int ic = m0 + tid; if (ic >= cnt) ic = cnt - 1;   // clamp; outputs suppressed
        if constexpr (ROUTED) {
            if constexpr (UP) { rmap[tid] = g_tok[e * T_TOK + ic]; omap[tid] = g_pair[e * T_TOK + ic]; }
            else {
                int pr = g_pair[e * T_TOK + ic];
                rmap[tid] = pr; omap[tid] = pr; smw[tid] = g_wt[pr];
            }
        } else { rmap[tid] = ic; omap[tid] = ic; if constexpr (!UP) smw[tid] = 1.f; }
    }
    __syncthreads();

    const int lane = tid & 31, wid = tid >> 5;
    const int wm = wid >> 2, wn = wid & 3;   // 2 x 4 warp grid, warp tile 64x32

    // staging geometry: 8 threads per row, each owns a float4 column chunk
    const int rbase = tid >> 3, cof = (tid & 7) * 4;
    const float* bsrc;
    if constexpr (UP) bsrc = (rbase & 1) ? W3 : W1;   // B-row parity fixed per thread
    else              bsrc = W1;

    // fragment-layout scatter constants
    const int s_a   = cof >> 3;                 // k-slice of this thread's 4 floats
    const int half  = (cof >> 2) & 1;           // high half of the 8-k slice?
    const int spair = s_a >> 1;
    const int slot  = (s_a & 1) * 2 + half;

    float acc[4][4][4];
#pragma unroll
    for (int mt = 0; mt < 4; mt++)
#pragma unroll
        for (int nt = 0; nt < 4; nt++)
#pragma unroll
            for (int r = 0; r < 4; r++) acc[mt][nt][r] = 0.f;

    float4 pa[4], pb[4];   // prefetch registers (coalesced LDG.128)
    auto GLOAD = [&](int kt) {
        const int k0 = kt * 32;
#pragma unroll
        for (int i = 0; i < 4; i++) {
            const int r = rbase + 32 * i;                       // A row in tile (0..127)
            pa[i] = *reinterpret_cast<const float4*>(Ap + (size_t)rmap[r] * KDIM + k0 + cof);
        }
#pragma unroll
        for (int i = 0; i < 4; i++) {
            const int n = rbase + 32 * i;                       // B row in tile (0..127)
            size_t row;
            if constexpr (UP) row = (size_t)((n0 + n) >> 1);
            else              row = (size_t)(n0 + n);
            pb[i] = *reinterpret_cast<const float4*>(bsrc + row * KDIM + k0 + cof);
        }
    };
    auto SSTORE = [&](int kt) {
        unsigned* Ab = dynsm + (kt & 1) * 8192;
        unsigned* Bb = Ab + 4096;
#pragma unroll
        for (int i = 0; i < 4; i++) {
            const int r = rbase + 32 * i;
            const int mt = r >> 4, rr = r & 15;
            const int q  = (rr >> 3) + 2 * half;
            const int lp = (rr & 7) * 4;
            const unsigned base = (unsigned)(((mt * 4 + s_a) * 32) * 4 + q);
            const float v[4] = { pa[i].x, pa[i].y, pa[i].z, pa[i].w };
#pragma unroll
            for (int e2 = 0; e2 < 4; e2++)
                Ab[base + (((lp + e2) ^ s_a) << 2)] = f2tf(v[e2]);
        }
#pragma unroll
        for (int i = 0; i < 4; i++) {
            const int n  = rbase + 32 * i;
            const int nt = n >> 3;
            const int lp = (n & 7) * 4;
            const unsigned base = (unsigned)(((nt * 2 + spair) * 32) * 4 + slot);
            const float v[4] = { pb[i].x, pb[i].y, pb[i].z, pb[i].w };
#pragma unroll
            for (int e2 = 0; e2 < 4; e2++)
                Bb[base + (((lp + e2) ^ spair) << 2)] = f2tf(v[e2]);
        }
    };

    // one sp-half of the mma burst (sp selects the B k-slice pair)
    auto MMA_HALF = [&](const unsigned* Ab, const unsigned* Bb, int sp) {
        uint4 bf[4];
#pragma unroll
        for (int nt = 0; nt < 4; nt++) {
            const int gnt = wn * 4 + nt;
            bf[nt] = *reinterpret_cast<const uint4*>(
                &Bb[((gnt * 2 + sp) * 32 + (lane ^ sp)) * 4]);
        }
#pragma unroll
        for (int sh = 0; sh < 2; sh++) {
            const int s = sp * 2 + sh;
            uint4 af[4];
#pragma unroll
            for (int mt = 0; mt < 4; mt++) {
                const int gmt = wm * 4 + mt;
                af[mt] = *reinterpret_cast<const uint4*>(
                    &Ab[((gmt * 4 + s) * 32 + (lane ^ s)) * 4]);
            }
#pragma unroll
            for (int mt = 0; mt < 4; mt++)
#pragma unroll
                for (int nt = 0; nt < 4; nt++) {
                    unsigned b2[2];
                    b2[0] = sh ? bf[nt].z : bf[nt].x;
                    b2[1] = sh ? bf[nt].w : bf[nt].y;
                    mma8(acc[mt][nt], reinterpret_cast<const unsigned*>(&af[mt]), b2);
                }
        }
    };

    // pipeline prologue: fill buffer 0, prefetch chunk 1
    GLOAD(0);
    SSTORE(0);
    GLOAD(1);
    __syncthreads();

    const int KIT = KDIM / 32;
    for (int kt = 0; kt < KIT; kt++) {
        const unsigned* Ab = dynsm + (kt & 1) * 8192;
        const unsigned* Bb = Ab + 4096;

        MMA_HALF(Ab, Bb, 0);
        if (kt + 1 < KIT) SSTORE(kt + 1);   // consumes pa/pb -> dead for 2nd half
        MMA_HALF(Ab, Bb, 1);
        if (kt + 2 < KIT) GLOAD(kt + 2);    // refills pa/pb; latency spans barrier+half
        __syncthreads();                    // single barrier per chunk
    }

    // ---- epilogue ----
#pragma unroll
    for (int mt = 0; mt < 4; mt++) {
        const int lr0 = wm * 64 + mt * 16 + (lane >> 2);
#pragma unroll
        for (int h = 0; h < 2; h++) {
            const int lr = lr0 + 8 * h;
            if (ROUTED && (m0 + lr) >= cnt) continue;
            const size_t orow = (size_t)omap[lr] * NTOT;
            if constexpr (UP) {
#pragma unroll
                for (int nt = 0; nt < 4; nt++) {
                    const int f = ((n0 + (wn * 4 + nt) * 8) >> 1) + (lane & 3);
                    const float u1 = acc[mt][nt][h * 2], u3 = acc[mt][nt][h * 2 + 1];
                    OUT[orow + f] = u1 / (1.f + __expf(-u1)) * u3;
                }
            } else {
                const float w = smw[lr];
#pragma unroll
                for (int nt = 0; nt < 4; nt++) {
                    const int g = n0 + (wn * 4 + nt) * 8 + 2 * (lane & 3);
                    float2 v;
                    v.x = acc[mt][nt][h * 2] * w;
                    v.y = acc[mt][nt][h * 2 + 1] * w;
                    if constexpr (ADDY) {   // fused combine: += 4 routed contributions
                        const size_t t4 = (size_t)omap[lr] * NTOPK;
#pragma unroll
                        for (int k = 0; k < NTOPK; k++) {
                            const float2 yv = *reinterpret_cast<const float2*>(
                                g_y + (t4 + k) * DMODEL + g);
                            v.x += yv.x; v.y += yv.y;
                        }
                    }
                    *reinterpret_cast<float2*>(OUT + orow + g) = v;
                }
            }
        }
    }
}

// ---------------- launch ----------------
extern "C" void kernel_launch(void* const* d_in, const int* in_sizes, int n_in,
                              void* d_out, int out_size) {
    const float* x   = (const float*)d_in[0];
    const float* gw  = (const float*)d_in[1];
    const float* w1  = (const float*)d_in[2];
    const float* w2  = (const float*)d_in[3];
    const float* w3  = (const float*)d_in[4];
    const float* sw1 = (const float*)d_in[5];
    const float* sw2 = (const float*)d_in[6];
    const float* sw3 = (const float*)d_in[7];
    float* out = (float*)d_out;

    // opt-in to 64KB dynamic SMEM (host-side attribute; not a stream operation)
    cudaFuncSetAttribute(gemm_tc<true,  true,  false, DMODEL,     INTERN>,
                         cudaFuncAttributeMaxDynamicSharedMemorySize, DYN_SMEM);
    cudaFuncSetAttribute(gemm_tc<true,  false, false, INTERN,     DMODEL>,
                         cudaFuncAttributeMaxDynamicSharedMemorySize, DYN_SMEM);
    cudaFuncSetAttribute(gemm_tc<false, true,  false, DMODEL,     2 * INTERN>,
                         cudaFuncAttributeMaxDynamicSharedMemorySize, DYN_SMEM);
    cudaFuncSetAttribute(gemm_tc<false, false, true,  2 * INTERN, DMODEL>,
                         cudaFuncAttributeMaxDynamicSharedMemorySize, DYN_SMEM);

    zero_kernel<<<1, 32>>>();
    gate_kernel<<<T_TOK / 4, 128>>>(x, gw);

    // routed: up (interleaved W1/W3 -> silu fused), then down (scaled into per-pair y)
    gemm_tc<true,  true,  false, DMODEL, INTERN>
        <<<dim3(T_TOK / 128, (2 * INTERN) / 128, NEXP), 256, DYN_SMEM>>>(x, w1, w3, nullptr);
    gemm_tc<true,  false, false, INTERN, DMODEL>
        <<<dim3(T_TOK / 128, DMODEL / 128, NEXP), 256, DYN_SMEM>>>(x, w2, nullptr, nullptr);

    // shared expert: up, then down writes z + sum_k y directly into d_out (fused combine)
    gemm_tc<false, true,  false, DMODEL, 2 * INTERN>
        <<<dim3(T_TOK / 128, (4 * INTERN) / 128, 1), 256, DYN_SMEM>>>(x, sw1, sw3, nullptr);
    gemm_tc<false, false, true,  2 * INTERN, DMODEL>
        <<<dim3(T_TOK / 128, DMODEL / 128, 1), 256, DYN_SMEM>>>(x, sw2, nullptr, out);
}

// round 16
// speedup vs baseline: 1.4683x; 1.0364x over previous
#include <cuda_runtime.h>
#include <cstdint>

#define T_TOK   4096
#define DMODEL  2048
#define NEXP    32
#define NTOPK   4
#define INTERN  1024
#define NPAIR   (T_TOK * NTOPK)
#define DYN_SMEM 65536   // 2 x (16KB A + 16KB B) double-buffered operands

// ---------------- device scratch (no runtime allocation allowed) ----------------
__device__ int   g_cnt[NEXP];
__device__ int   g_tok[NEXP * T_TOK];
__device__ int   g_pair[NEXP * T_TOK];
__device__ float g_wt[NPAIR];
__device__ float g_h [(size_t)NPAIR * INTERN];      // routed up output (per pair)
__device__ float g_y [(size_t)NPAIR * DMODEL];      // routed down output (per pair, scaled)
__device__ float g_hs[(size_t)T_TOK * 2 * INTERN];  // shared up output

// ---------------- helpers ----------------
__device__ __forceinline__ unsigned f2tf(float x) {
    unsigned u; asm("cvt.rna.tf32.f32 %0, %1;" : "=r"(u) : "f"(x)); return u;
}
__device__ __forceinline__ void mma8(float* d, const unsigned* a, const unsigned* b) {
    asm volatile(
        "mma.sync.aligned.m16n8k8.row.col.f32.tf32.tf32.f32 "
        "{%0,%1,%2,%3},{%4,%5,%6,%7},{%8,%9},{%0,%1,%2,%3};\n"
        : "+f"(d[0]), "+f"(d[1]), "+f"(d[2]), "+f"(d[3])
        : "r"(a[0]), "r"(a[1]), "r"(a[2]), "r"(a[3]), "r"(b[0]), "r"(b[1]));
}

// ---------------- kernel 0: zero expert counters ----------------
__global__ void zero_kernel() {
    if (threadIdx.x < NEXP) g_cnt[threadIdx.x] = 0;
}

// ---------------- kernel 1: gate, 4 tokens per block ----------------
__global__ void __launch_bounds__(128) gate_kernel(const float* __restrict__ X,
                                                   const float* __restrict__ GW) {
    __shared__ float xs[4 * DMODEL];
    __shared__ float logits[4][NEXP];
    const int t0 = blockIdx.x * 4, tid = threadIdx.x;

    const float4* xr = reinterpret_cast<const float4*>(X + (size_t)t0 * DMODEL);
#pragma unroll
    for (int i = 0; i < 16; i++)
        reinterpret_cast<float4*>(xs)[tid + 128 * i] = xr[tid + 128 * i];
    __syncthreads();

    const int e = tid >> 2, p = tid & 3;
    const float4* gw4 = reinterpret_cast<const float4*>(GW + (size_t)e * DMODEL + p * 512);
    const float4* x0 = reinterpret_cast<const float4*>(xs + 0 * DMODEL + p * 512);
    const float4* x1 = reinterpret_cast<const float4*>(xs + 1 * DMODEL + p * 512);
    const float4* x2 = reinterpret_cast<const float4*>(xs + 2 * DMODEL + p * 512);
    const float4* x3 = reinterpret_cast<const float4*>(xs + 3 * DMODEL + p * 512);
    float a0 = 0.f, a1 = 0.f, a2 = 0.f, a3 = 0.f;
#pragma unroll 4
    for (int d = 0; d < 128; d++) {
        const float4 b = gw4[d];
        float4 a;
        a = x0[d]; a0 += a.x * b.x + a.y * b.y + a.z * b.z + a.w * b.w;
        a = x1[d]; a1 += a.x * b.x + a.y * b.y + a.z * b.z + a.w * b.w;
        a = x2[d]; a2 += a.x * b.x + a.y * b.y + a.z * b.z + a.w * b.w;
        a = x3[d]; a3 += a.x * b.x + a.y * b.y + a.z * b.z + a.w * b.w;
    }
#pragma unroll
    for (int o = 2; o; o >>= 1) {
        a0 += __shfl_down_sync(0xffffffffu, a0, o, 4);
        a1 += __shfl_down_sync(0xffffffffu, a1, o, 4);
        a2 += __shfl_down_sync(0xffffffffu, a2, o, 4);
        a3 += __shfl_down_sync(0xffffffffu, a3, o, 4);
    }
    if (p == 0) { logits[0][e] = a0; logits[1][e] = a1; logits[2][e] = a2; logits[3][e] = a3; }
    __syncthreads();

    if (tid < 32) {
        for (int t = 0; t < 4; t++) {
            float v = logits[t][tid];
            float m = v;
#pragma unroll
            for (int o = 16; o; o >>= 1) m = fmaxf(m, __shfl_xor_sync(0xffffffffu, m, o));
            float ex = __expf(v - m), sum = ex;
#pragma unroll
            for (int o = 16; o; o >>= 1) sum += __shfl_xor_sync(0xffffffffu, sum, o);
            float val = ex / sum;
#pragma unroll
            for (int k = 0; k < NTOPK; k++) {
                float bv = val; int bi = tid;
#pragma unroll
                for (int o = 16; o; o >>= 1) {  // argmax, ties -> lower index
                    float ov = __shfl_xor_sync(0xffffffffu, bv, o);
                    int   oi = __shfl_xor_sync(0xffffffffu, bi, o);
                    if (ov > bv || (ov == bv && oi < bi)) { bv = ov; bi = oi; }
                }
                if (tid == 0) {
                    int pr = (t0 + t) * NTOPK + k;
                    g_wt[pr] = bv;
                    int slot = atomicAdd(&g_cnt[bi], 1);
                    g_tok[bi * T_TOK + slot]  = t0 + t;
                    g_pair[bi * T_TOK + slot] = pr;
                }
                if (tid == bi) val = -1e30f;
            }
        }
    }
}

// ================= unified tf32 mma.sync GEMM =================
// CTA tile M=128, N=128, K-chunk=32, double-buffered dynamic SMEM (64KB), one
// barrier per chunk. NOW 128 threads / 4 warps (2m x 2n), WARP TILE 64x64:
// 128 mmas per warp-chunk from 32 LDS.128 -> 1.0 wavefront/mma (was 1.5).
// acc = 128 regs/thread; 2 CTAs/SM still fit the RF (2*128*~240 < 64K) so the
// R15 cross-CTA bubble hiding is preserved. SMEM fragment layout is identical
// to R15; only the staging thread-mapping (128 thr) and consumer warp grid
// change. SSTORE placed between the two sp-halves of the mma burst and GLOAD
// after, keeping the 64 prefetch regs off the register peak.
//
// UP mode: B rows interleave W1/W3; C fragment holds (u1,u3) adjacent -> silu
// fused in epilogue, NTOT = N/2 features. DOWN: GEMM * routing weight; ADDY
// additionally adds the 4 routed per-pair y rows (fused combine).
template <bool ROUTED, bool UP, bool ADDY, int KDIM, int NTOT>
__global__ void __launch_bounds__(128, 2) gemm_tc(const float* __restrict__ Xin,
                                                  const float* __restrict__ Bw1,
                                                  const float* __restrict__ Bw3,
                                                  float* __restrict__ OUTp) {
    extern __shared__ unsigned dynsm[];   // [buf][A 4096 | B 4096] words
    __shared__ int   rmap[128], omap[128];
    __shared__ float smw[128];

    const int e  = blockIdx.z;
    const int m0 = blockIdx.x * 128;
    const int n0 = blockIdx.y * 128;
    int cnt;
    const float *Ap, *W1, *W3 = nullptr;
    float* OUT;
    if constexpr (ROUTED) {
        cnt = g_cnt[e];
        if (m0 >= cnt) return;
        if constexpr (UP) {
            const size_t eo = (size_t)e * INTERN * DMODEL;
            W1 = Bw1 + eo; W3 = Bw3 + eo; Ap = Xin; OUT = g_h;
        } else {
            W1 = Bw1 + (size_t)e * DMODEL * INTERN; Ap = g_h; OUT = g_y;
        }
    } else {
        cnt = T_TOK;
        if constexpr (UP) { W1 = Bw1; W3 = Bw3; Ap = Xin; OUT = g_hs; }
        else              { W1 = Bw1; Ap = g_hs; OUT = OUTp; }
    }

    const int tid = threadIdx.x;
    {   // 128 threads load all 128 map entries
        int ic = m0 + tid; if (ic >= cnt) ic = cnt - 1;   // clamp; outputs suppressed
        if constexpr (ROUTED) {
            if constexpr (UP) { rmap[tid] = g_tok[e * T_TOK + ic]; omap[tid] = g_pair[e * T_TOK + ic]; }
            else {
                int pr = g_pair[e * T_TOK + ic];
                rmap[tid] = pr; omap[tid] = pr; smw[tid] = g_wt[pr];
            }
        } else { rmap[tid] = ic; omap[tid] = ic; if constexpr (!UP) smw[tid] = 1.f; }
    }
    __syncthreads();

    const int lane = tid & 31, wid = tid >> 5;
    const int wm = wid >> 1, wn = wid & 1;   // 2 x 2 warp grid, warp tile 64x64

    // staging geometry: 8 threads per row (16 rows per pass, 8 passes)
    const int rbase = tid >> 3, cof = (tid & 7) * 4;
    const float* bsrc;
    if constexpr (UP) bsrc = (rbase & 1) ? W3 : W1;   // B-row parity fixed per thread
    else              bsrc = W1;

    // fragment-layout scatter constants
    const int s_a   = cof >> 3;                 // k-slice of this thread's 4 floats
    const int half  = (cof >> 2) & 1;           // high half of the 8-k slice?
    const int spair = s_a >> 1;
    const int slot  = (s_a & 1) * 2 + half;

    float acc[4][8][4];
#pragma unroll
    for (int mt = 0; mt < 4; mt++)
#pragma unroll
        for (int nt = 0; nt < 8; nt++)
#pragma unroll
            for (int r = 0; r < 4; r++) acc[mt][nt][r] = 0.f;

    float4 pa[8], pb[8];   // prefetch registers (coalesced LDG.128)
    auto GLOAD = [&](int kt) {
        const int k0 = kt * 32;
#pragma unroll
        for (int i = 0; i < 8; i++) {
            const int r = rbase + 16 * i;                       // A row in tile (0..127)
            pa[i] = *reinterpret_cast<const float4*>(Ap + (size_t)rmap[r] * KDIM + k0 + cof);
        }
#pragma unroll
        for (int i = 0; i < 8; i++) {
            const int n = rbase + 16 * i;                       // B row in tile (0..127)
            size_t row;
            if constexpr (UP) row = (size_t)((n0 + n) >> 1);
            else              row = (size_t)(n0 + n);
            pb[i] = *reinterpret_cast<const float4*>(bsrc + row * KDIM + k0 + cof);
        }
    };
    auto SSTORE = [&](int kt) {
        unsigned* Ab = dynsm + (kt & 1) * 8192;
        unsigned* Bb = Ab + 4096;
#pragma unroll
        for (int i = 0; i < 8; i++) {
            const int r = rbase + 16 * i;
            const int mt = r >> 4, rr = r & 15;
            const int q  = (rr >> 3) + 2 * half;
            const int lp = (rr & 7) * 4;
            const unsigned base = (unsigned)(((mt * 4 + s_a) * 32) * 4 + q);
            const float v[4] = { pa[i].x, pa[i].y, pa[i].z, pa[i].w };
#pragma unroll
            for (int e2 = 0; e2 < 4; e2++)
                Ab[base + (((lp + e2) ^ s_a) << 2)] = f2tf(v[e2]);
        }
#pragma unroll
        for (int i = 0; i < 8; i++) {
            const int n  = rbase + 16 * i;
            const int nt = n >> 3;
            const int lp = (n & 7) * 4;
            const unsigned base = (unsigned)(((nt * 2 + spair) * 32) * 4 + slot);
            const float v[4] = { pb[i].x, pb[i].y, pb[i].z, pb[i].w };
#pragma unroll
            for (int e2 = 0; e2 < 4; e2++)
                Bb[base + (((lp + e2) ^ spair) << 2)] = f2tf(v[e2]);
        }
    };

    // one sp-half of the mma burst: 8 af + 8 bf LDS.128, 64 mmas
    auto MMA_SP = [&](const unsigned* Ab, const unsigned* Bb, int sp) {
        uint4 af[2][4];
#pragma unroll
        for (int sh = 0; sh < 2; sh++) {
            const int s = sp * 2 + sh;
#pragma unroll
            for (int mt = 0; mt < 4; mt++) {
                const int gmt = wm * 4 + mt;
                af[sh][mt] = *reinterpret_cast<const uint4*>(
                    &Ab[((gmt * 4 + s) * 32 + (lane ^ s)) * 4]);
            }
        }
#pragma unroll
        for (int nt = 0; nt < 8; nt++) {
            const int gnt = wn * 8 + nt;
            const uint4 bf = *reinterpret_cast<const uint4*>(
                &Bb[((gnt * 2 + sp) * 32 + (lane ^ sp)) * 4]);
#pragma unroll
            for (int sh = 0; sh < 2; sh++) {
                unsigned b2[2];
                b2[0] = sh ? bf.z : bf.x;
                b2[1] = sh ? bf.w : bf.y;
#pragma unroll
                for (int mt = 0; mt < 4; mt++)
                    mma8(acc[mt][nt], reinterpret_cast<const unsigned*>(&af[sh][mt]), b2);
            }
        }
    };

    // pipeline prologue: fill buffer 0, prefetch chunk 1
    GLOAD(0);
    SSTORE(0);
    GLOAD(1);
    __syncthreads();

    const int KIT = KDIM / 32;
    for (int kt = 0; kt < KIT; kt++) {
        const unsigned* Ab = dynsm + (kt & 1) * 8192;
        const unsigned* Bb = Ab + 4096;

        MMA_SP(Ab, Bb, 0);
        if (kt + 1 < KIT) SSTORE(kt + 1);   // consumes pa/pb -> dead for 2nd half
        MMA_SP(Ab, Bb, 1);
        if (kt + 2 < KIT) GLOAD(kt + 2);    // refills pa/pb; latency spans barrier
        __syncthreads();                    // single barrier per chunk
    }

    // ---- epilogue ----
#pragma unroll
    for (int mt = 0; mt < 4; mt++) {
        const int lr0 = wm * 64 + mt * 16 + (lane >> 2);
#pragma unroll
        for (int h = 0; h < 2; h++) {
            const int lr = lr0 + 8 * h;
            if (ROUTED && (m0 + lr) >= cnt) continue;
            const size_t orow = (size_t)omap[lr] * NTOT;
            if constexpr (UP) {
#pragma unroll
                for (int nt = 0; nt < 8; nt++) {
                    const int f = ((n0 + (wn * 8 + nt) * 8) >> 1) + (lane & 3);
                    const float u1 = acc[mt][nt][h * 2], u3 = acc[mt][nt][h * 2 + 1];
                    OUT[orow + f] = u1 / (1.f + __expf(-u1)) * u3;
                }
            } else {
                const float w = smw[lr];
#pragma unroll
                for (int nt = 0; nt < 8; nt++) {
                    const int g = n0 + (wn * 8 + nt) * 8 + 2 * (lane & 3);
                    float2 v;
                    v.x = acc[mt][nt][h * 2] * w;
                    v.y = acc[mt][nt][h * 2 + 1] * w;
                    if constexpr (ADDY) {   // fused combine: += 4 routed contributions
                        const size_t t4 = (size_t)omap[lr] * NTOPK;
#pragma unroll
                        for (int k = 0; k < NTOPK; k++) {
                            const float2 yv = *reinterpret_cast<const float2*>(
                                g_y + (t4 + k) * DMODEL + g);
                            v.x += yv.x; v.y += yv.y;
                        }
                    }
                    *reinterpret_cast<float2*>(OUT + orow + g) = v;
                }
            }
        }
    }
}

// ---------------- launch ----------------
extern "C" void kernel_launch(void* const* d_in, const int* in_sizes, int n_in,
                              void* d_out, int out_size) {
    const float* x   = (const float*)d_in[0];
    const float* gw  = (const float*)d_in[1];
    const float* w1  = (const float*)d_in[2];
    const float* w2  = (const float*)d_in[3];
    const float* w3  = (const float*)d_in[4];
    const float* sw1 = (const float*)d_in[5];
    const float* sw2 = (const float*)d_in[6];
    const float* sw3 = (const float*)d_in[7];
    float* out = (float*)d_out;

    // opt-in to 64KB dynamic SMEM (host-side attribute; not a stream operation)
    cudaFuncSetAttribute(gemm_tc<true,  true,  false, DMODEL,     INTERN>,
                         cudaFuncAttributeMaxDynamicSharedMemorySize, DYN_SMEM);
    cudaFuncSetAttribute(gemm_tc<true,  false, false, INTERN,     DMODEL>,
                         cudaFuncAttributeMaxDynamicSharedMemorySize, DYN_SMEM);
    cudaFuncSetAttribute(gemm_tc<false, true,  false, DMODEL,     2 * INTERN>,
                         cudaFuncAttributeMaxDynamicSharedMemorySize, DYN_SMEM);
    cudaFuncSetAttribute(gemm_tc<false, false, true,  2 * INTERN, DMODEL>,
                         cudaFuncAttributeMaxDynamicSharedMemorySize, DYN_SMEM);

    zero_kernel<<<1, 32>>>();
    gate_kernel<<<T_TOK / 4, 128>>>(x, gw);

    // routed: up (interleaved W1/W3 -> silu fused), then down (scaled into per-pair y)
    gemm_tc<true,  true,  false, DMODEL, INTERN>
        <<<dim3(T_TOK / 128, (2 * INTERN) / 128, NEXP), 128, DYN_SMEM>>>(x, w1, w3, nullptr);
    gemm_tc<true,  false, false, INTERN, DMODEL>
        <<<dim3(T_TOK / 128, DMODEL / 128, NEXP), 128, DYN_SMEM>>>(x, w2, nullptr, nullptr);

    // shared expert: up, then down writes z + sum_k y directly into d_out (fused combine)
    gemm_tc<false, true,  false, DMODEL, 2 * INTERN>
        <<<dim3(T_TOK / 128, (4 * INTERN) / 128, 1), 128, DYN_SMEM>>>(x, sw1, sw3, nullptr);
    gemm_tc<false, false, true,  2 * INTERN, DMODEL>
        <<<dim3(T_TOK / 128, DMODEL / 128, 1), 128, DYN_SMEM>>>(x, sw2, nullptr, out);
}